// round 6
// baseline (speedup 1.0000x reference)
#include <cuda_runtime.h>
#include <cstdint>

typedef unsigned long long ull;

// Problem constants
#define BATCH 8
#define CIN 128
#define COUT 128
#define HW 4096            // 64*64
#define PLANE 524288       // CIN*HW floats per batch
#define NPIX 32768         // BATCH*HW
#define K2 9

// Scratch (device globals: allocation-free per harness rules)
__device__ float g_xT[BATCH * HW * CIN];     // NHWC transpose of x
__device__ float g_off[NPIX * 18];           // offsets, [p][18]
__device__ ull   g_wTd[K2 * CIN * COUT];     // w_conv dup pairs {w,w}: [tap][ci][o]

#define FFMA2(acc, a, b) \
    asm("fma.rn.f32x2 %0, %1, %2, %0;" : "+l"(acc) : "l"(a), "l"(b))
#define DUP64(d, f) asm("mov.b64 %0, {%1, %1};" : "=l"(d) : "f"(f))
#define PACK64(d, lo, hi) asm("mov.b64 %0, {%1, %2};" : "=l"(d) : "f"(lo), "f"(hi))
#define CP_ASYNC16(dst, src) \
    asm volatile("cp.async.cg.shared.global [%0], [%1], 16;" :: "r"(dst), "l"(src) : "memory")
#define CP_COMMIT() asm volatile("cp.async.commit_group;" ::: "memory")
#define CP_WAIT0()  asm volatile("cp.async.wait_group 0;" ::: "memory")

__device__ __forceinline__ uint32_t smem_u32(const void* p) {
    uint32_t a;
    asm("{ .reg .u64 t; cvta.to.shared.u64 t, %1; cvt.u32.u64 %0, t; }" : "=r"(a) : "l"(p));
    return a;
}

// ---------------------------------------------------------------------------
// Kernel 1: NCHW -> NHWC transpose of x
// ---------------------------------------------------------------------------
__global__ void dcb_transpose_kernel(const float* __restrict__ x) {
    __shared__ float tile[32][33];
    int b   = blockIdx.z;
    int ci0 = blockIdx.y * 32;
    int p0  = blockIdx.x * 32;
    int tx = threadIdx.x, ty = threadIdx.y;   // 32 x 8
    const float* xb = x + (size_t)b * PLANE;
    #pragma unroll
    for (int k = 0; k < 32; k += 8)
        tile[ty + k][tx] = xb[(ci0 + ty + k) * HW + p0 + tx];
    __syncthreads();
    float* xTb = g_xT + (size_t)b * PLANE;
    #pragma unroll
    for (int k = 0; k < 32; k += 8)
        xTb[(p0 + ty + k) * CIN + ci0 + tx] = tile[tx][ty + k];
}

// ---------------------------------------------------------------------------
// Kernel 2: w_conv [o][i][ky][kx] -> g_wTd [tap][i][o] with {w,w} duplication
// ---------------------------------------------------------------------------
__global__ void dcb_wprep_kernel(const float* __restrict__ wc) {
    int m = blockIdx.x * 256 + threadIdx.x;
    if (m < K2 * CIN * COUT) {
        int tap = m / (CIN * COUT);
        int r   = m - tap * (CIN * COUT);
        int i   = r >> 7;
        int o   = r & 127;
        float w = wc[o * (CIN * K2) + i * K2 + tap];
        ull d; DUP64(d, w);
        g_wTd[m] = d;
    }
}

// ---------------------------------------------------------------------------
// Kernel 3: offset conv, weights hoisted over 4 pixels (unchanged from R5).
// smem: ws2[tap][cpair(9)][ci(128)] of float2 = 82944 B
// ---------------------------------------------------------------------------
__global__ __launch_bounds__(256) void dcb_offset_kernel(const float* __restrict__ wofs) {
    extern __shared__ float ws[];
    float2* ws2 = (float2*)ws;
    int tid = threadIdx.x;
    for (int idx = tid; idx < K2 * 9 * CIN; idx += 256) {
        int tap = idx / (9 * CIN);
        int r   = idx - tap * (9 * CIN);
        int cp  = r >> 7;
        int ci  = r & 127;
        float w0 = wofs[(2 * cp)     * (CIN * K2) + ci * K2 + tap];
        float w1 = wofs[(2 * cp + 1) * (CIN * K2) + ci * K2 + tap];
        ws2[(tap * 9 + cp) * 128 + ci] = make_float2(w0, w1);
    }
    __syncthreads();

    int lane = tid & 31;
    int warp = tid >> 5;
    int wg = blockIdx.x * 8 + warp;
    int ci4 = lane * 4;

    for (int q4 = 0; q4 < 4; q4++) {
        int pbase = wg * 16 + q4 * 4;
        int b   = pbase >> 12;
        const float* xb = g_xT + (size_t)b * PLANE;

        ull acc2[4][9];
        #pragma unroll
        for (int j = 0; j < 4; j++)
            #pragma unroll
            for (int c = 0; c < 9; c++) acc2[j][c] = 0ull;

        #pragma unroll
        for (int tap = 0; tap < 9; tap++) {
            ull ax[4][4];
            #pragma unroll
            for (int j = 0; j < 4; j++) {
                int pix = (pbase + j) & 4095;
                int y   = pix >> 6;
                int x0  = pix & 63;
                int yy = y - 1 + tap / 3;
                int xx = x0 - 1 + tap % 3;
                float4 xv = make_float4(0.f, 0.f, 0.f, 0.f);
                if (yy >= 0 && yy <= 63 && xx >= 0 && xx <= 63)
                    xv = *(const float4*)&xb[(yy * 64 + xx) * CIN + ci4];
                DUP64(ax[j][0], xv.x);
                DUP64(ax[j][1], xv.y);
                DUP64(ax[j][2], xv.z);
                DUP64(ax[j][3], xv.w);
            }
            #pragma unroll
            for (int cp = 0; cp < 9; cp++) {
                const ulonglong2* wp =
                    (const ulonglong2*)(ws2 + (tap * 9 + cp) * 128 + ci4);
                ulonglong2 wA = wp[0];
                ulonglong2 wB = wp[1];
                #pragma unroll
                for (int j = 0; j < 4; j++) {
                    FFMA2(acc2[j][cp], ax[j][0], wA.x);
                    FFMA2(acc2[j][cp], ax[j][1], wA.y);
                    FFMA2(acc2[j][cp], ax[j][2], wB.x);
                    FFMA2(acc2[j][cp], ax[j][3], wB.y);
                }
            }
        }
        #pragma unroll
        for (int j = 0; j < 4; j++) {
            float acc[18];
            #pragma unroll
            for (int cp = 0; cp < 9; cp++)
                asm("mov.b64 {%0, %1}, %2;"
                    : "=f"(acc[2 * cp]), "=f"(acc[2 * cp + 1]) : "l"(acc2[j][cp]));
            #pragma unroll
            for (int c = 0; c < 18; c++) {
                #pragma unroll
                for (int s = 16; s > 0; s >>= 1)
                    acc[c] += __shfl_xor_sync(0xffffffffu, acc[c], s);
            }
            if (lane < 18) {
                float v = 0.f;
                #pragma unroll
                for (int c = 0; c < 18; c++) if (lane == c) v = acc[c];
                g_off[(pbase + j) * 18 + lane] = v;
            }
        }
    }
}

// ---------------------------------------------------------------------------
// Kernel 4: deformable gather + pixel-pair FFMA2 GEMM. All 16 warps compute.
// Tile 128 px x 128 co, 512 threads, thread = 8 px x 4 co.
// v smem: [128 ci][64 px-pair u64, interleaved pos(q)=(q&3)*16+(q>>2), row 544B]
// w smem: [128 ci][128 co dup u64] = 1024B/row, staged per tap via cp.async.
// SMEM: v 69632 | w 131072 | m_idx 2048 | m_w 2048 = 204800 B
// ---------------------------------------------------------------------------
#define VROWB    544
#define SM_V     0
#define SM_W     69632
#define SM_MIDX  200704
#define SM_MW    202752
#define SMEM_DEF 204800

__global__ __launch_bounds__(512, 1) void dcb_deform_kernel(float* __restrict__ out) {
    extern __shared__ char sm[];
    uint32_t smb = smem_u32(sm);
    int tid  = threadIdx.x;

    int p0    = blockIdx.x * 128;
    int b     = p0 >> 12;
    int bbase = b << 19;                     // b * PLANE
    int pix0  = p0 & 4095;
    const float* __restrict__ xb = g_xT + bbase;

    int*   m_idx = (int*)(sm + SM_MIDX);
    float* m_w   = (float*)(sm + SM_MW);

    // GEMM roles
    int pxg = tid & 15;                      // 16 groups of 4 px-pairs (8 px)
    int cog = tid >> 4;                      // 32 groups of 4 couts
    // gather roles
    int q  = tid & 63;                       // pixel pair (2q, 2q+1)
    int c8 = tid >> 6;                       // ci chunk: c8*16 .. +15
    int pos8 = ((q & 3) * 16 + (q >> 2)) * 8;

    ull acc[16];
    #pragma unroll
    for (int i = 0; i < 16; i++) acc[i] = 0ull;

    for (int tap = 0; tap < 9; tap++) {
        // ---- meta for 128 pixels (runs in shadow of previous GEMM tail) ----
        if (tid < 128) {
            int j   = tid;
            int p   = p0 + j;
            int pix = pix0 + j;
            int y   = pix >> 6;
            int xx  = pix & 63;
            float dy = g_off[p * 18 + tap * 2];
            float dx = g_off[p * 18 + tap * 2 + 1];
            float py = (float)(y - 1 + tap / 3) + dy;
            float px = (float)(xx - 1 + tap % 3) + dx;
            float y0f = floorf(py), x0f = floorf(px);
            float fy = py - y0f, fx = px - x0f;
            float vy0 = (y0f >= 0.f  && y0f <= 63.f) ? 1.f : 0.f;
            float vy1 = (y0f >= -1.f && y0f <= 62.f) ? 1.f : 0.f;
            float vx0 = (x0f >= 0.f  && x0f <= 63.f) ? 1.f : 0.f;
            float vx1 = (x0f >= -1.f && x0f <= 62.f) ? 1.f : 0.f;
            int yi0 = (int)fminf(fmaxf(y0f,       0.f), 63.f);
            int yi1 = (int)fminf(fmaxf(y0f + 1.f, 0.f), 63.f);
            int xi0 = (int)fminf(fmaxf(x0f,       0.f), 63.f);
            int xi1 = (int)fminf(fmaxf(x0f + 1.f, 0.f), 63.f);
            m_idx[j * 4 + 0] = (yi0 * 64 + xi0) << 7;
            m_idx[j * 4 + 1] = (yi0 * 64 + xi1) << 7;
            m_idx[j * 4 + 2] = (yi1 * 64 + xi0) << 7;
            m_idx[j * 4 + 3] = (yi1 * 64 + xi1) << 7;
            m_w[j * 4 + 0] = (1.f - fy) * (1.f - fx) * vy0 * vx0;
            m_w[j * 4 + 1] = (1.f - fy) * fx         * vy0 * vx1;
            m_w[j * 4 + 2] = fy         * (1.f - fx) * vy1 * vx0;
            m_w[j * 4 + 3] = fy         * fx         * vy1 * vx1;
        }
        __syncthreads();     // A: prev GEMM done (v/w free) + meta visible

        // ---- stage W[tap] via cp.async (overlaps gather LDGs below) ----
        {
            uint32_t dst = smb + SM_W + tid * 16;
            const char* src = (const char*)g_wTd + tap * 131072 + tid * 16;
            #pragma unroll
            for (int k = 0; k < 16; k++)
                CP_ASYNC16(dst + k * 8192, src + k * 8192);
            CP_COMMIT();
        }

        // ---- gather: pixel pair (2q, 2q+1), ci chunk c8*16..+15 ----
        {
            int4   mi0 = *(const int4*)  &m_idx[(2 * q)     * 4];
            float4 mw0 = *(const float4*)&m_w  [(2 * q)     * 4];
            int4   mi1 = *(const int4*)  &m_idx[(2 * q + 1) * 4];
            float4 mw1 = *(const float4*)&m_w  [(2 * q + 1) * 4];
            #pragma unroll
            for (int g = 0; g < 4; g++) {
                int ci0 = c8 * 16 + g * 4;
                float4 a0 = *(const float4*)&xb[mi0.x + ci0];
                float4 a1 = *(const float4*)&xb[mi0.y + ci0];
                float4 a2 = *(const float4*)&xb[mi0.z + ci0];
                float4 a3 = *(const float4*)&xb[mi0.w + ci0];
                float4 b0 = *(const float4*)&xb[mi1.x + ci0];
                float4 b1 = *(const float4*)&xb[mi1.y + ci0];
                float4 b2 = *(const float4*)&xb[mi1.z + ci0];
                float4 b3 = *(const float4*)&xb[mi1.w + ci0];
                float4 v0, v1;
                v0.x = mw0.x * a0.x + mw0.y * a1.x + mw0.z * a2.x + mw0.w * a3.x;
                v0.y = mw0.x * a0.y + mw0.y * a1.y + mw0.z * a2.y + mw0.w * a3.y;
                v0.z = mw0.x * a0.z + mw0.y * a1.z + mw0.z * a2.z + mw0.w * a3.z;
                v0.w = mw0.x * a0.w + mw0.y * a1.w + mw0.z * a2.w + mw0.w * a3.w;
                v1.x = mw1.x * b0.x + mw1.y * b1.x + mw1.z * b2.x + mw1.w * b3.x;
                v1.y = mw1.x * b0.y + mw1.y * b1.y + mw1.z * b2.y + mw1.w * b3.y;
                v1.z = mw1.x * b0.z + mw1.y * b1.z + mw1.z * b2.z + mw1.w * b3.z;
                v1.w = mw1.x * b0.w + mw1.y * b1.w + mw1.z * b2.w + mw1.w * b3.w;
                ull pr;
                PACK64(pr, v0.x, v1.x); *(ull*)(sm + SM_V + (ci0 + 0) * VROWB + pos8) = pr;
                PACK64(pr, v0.y, v1.y); *(ull*)(sm + SM_V + (ci0 + 1) * VROWB + pos8) = pr;
                PACK64(pr, v0.z, v1.z); *(ull*)(sm + SM_V + (ci0 + 2) * VROWB + pos8) = pr;
                PACK64(pr, v0.w, v1.w); *(ull*)(sm + SM_V + (ci0 + 3) * VROWB + pos8) = pr;
            }
        }
        CP_WAIT0();
        __syncthreads();     // C: v + w staged

        // ---- GEMM: 128 ci, 16 FFMA2 per ci per thread ----
        {
            const char* ap = sm + SM_V + pxg * 8;
            const char* bp = sm + SM_W + cog * 32;
            #pragma unroll 4
            for (int ci = 0; ci < 128; ci++) {
                ull a0 = *(const ull*)(ap);
                ull a1 = *(const ull*)(ap + 128);
                ull a2 = *(const ull*)(ap + 256);
                ull a3 = *(const ull*)(ap + 384);
                ulonglong2 w01 = *(const ulonglong2*)(bp);
                ulonglong2 w23 = *(const ulonglong2*)(bp + 16);
                FFMA2(acc[0],  a0, w01.x); FFMA2(acc[1],  a0, w01.y);
                FFMA2(acc[2],  a0, w23.x); FFMA2(acc[3],  a0, w23.y);
                FFMA2(acc[4],  a1, w01.x); FFMA2(acc[5],  a1, w01.y);
                FFMA2(acc[6],  a1, w23.x); FFMA2(acc[7],  a1, w23.y);
                FFMA2(acc[8],  a2, w01.x); FFMA2(acc[9],  a2, w01.y);
                FFMA2(acc[10], a2, w23.x); FFMA2(acc[11], a2, w23.y);
                FFMA2(acc[12], a3, w01.x); FFMA2(acc[13], a3, w01.y);
                FFMA2(acc[14], a3, w23.x); FFMA2(acc[15], a3, w23.y);
                ap += VROWB;
                bp += 1024;
            }
        }
    }

    // ---- epilogue: smem transpose (reuse v region) -> coalesced NCHW ----
    __syncthreads();
    float* s_out = (float*)sm;               // [128 co][132 px padded]
    #pragma unroll
    for (int k = 0; k < 4; k++) {
        int px = pxg * 8 + k * 2;            // pair (px, px+1)
        #pragma unroll
        for (int c = 0; c < 4; c++) {
            int co = cog * 4 + c;
            *(ull*)(s_out + co * 132 + px) = acc[k * 4 + c];
        }
    }
    __syncthreads();
    {
        int co   = tid >> 2;
        int part = tid & 3;
        const float4* src = (const float4*)(s_out + co * 132 + part * 32);
        float4* dst = (float4*)(out + bbase + co * HW + pix0 + part * 32);
        #pragma unroll
        for (int i = 0; i < 8; i++) dst[i] = src[i];
    }
}

// ---------------------------------------------------------------------------
extern "C" void kernel_launch(void* const* d_in, const int* in_sizes, int n_in,
                              void* d_out, int out_size) {
    const float* x = nullptr;
    const float* wofs = nullptr;
    const float* wconv = nullptr;
    for (int i = 0; i < n_in; i++) {
        if      (in_sizes[i] == BATCH * CIN * HW) x     = (const float*)d_in[i];
        else if (in_sizes[i] == 18 * CIN * K2)    wofs  = (const float*)d_in[i];
        else if (in_sizes[i] == COUT * CIN * K2)  wconv = (const float*)d_in[i];
    }
    float* out = (float*)d_out;

    cudaFuncSetAttribute(dcb_offset_kernel,
                         cudaFuncAttributeMaxDynamicSharedMemorySize, 82944);
    cudaFuncSetAttribute(dcb_deform_kernel,
                         cudaFuncAttributeMaxDynamicSharedMemorySize, SMEM_DEF);

    dim3 tb(32, 8);
    dim3 tg(HW / 32, CIN / 32, BATCH);
    dcb_transpose_kernel<<<tg, tb>>>(x);

    dcb_wprep_kernel<<<(K2 * CIN * COUT + 255) / 256, 256>>>(wconv);

    dcb_offset_kernel<<<256, 256, 82944>>>(wofs);

    dcb_deform_kernel<<<NPIX / 128, 512, SMEM_DEF>>>(out);
}